// round 11
// baseline (speedup 1.0000x reference)
#include <cuda_runtime.h>

#define B_   16
#define N_   1024
#define H_   224
#define W_   224
#define W2   112              // W_/2
#define KS   23
#define HALF 11
#define RPB  14               // output rows per block
#define TILES_Y 16            // H_/RPB
#define STRIP 36              // RPB+KS-1 hist rows
#define NTHR 256
#define NBLK (B_ * TILES_Y)   // 256 blocks

#define HIST_F (STRIP * W_)   // 8064 floats (32256 B)
#define BW     247            // odd row stride; 247%32=23 coprime -> conflict-free
#define B_F    (RPB * BW)     // 3458 floats (13832 B)
#define YRT    7              // y-conv rows per unit -> 2*112 = 224 units
#define XT     14             // x-conv cols per unit -> 16*14 = 224 units
#define XTILES (W_ / XT)      // 16

// Compile-time Gaussian(sigma=3, ks=23), L1-normalized. w[j] = exp(-(j-11)^2/18)/S.
// Immediate operands -> FFMA-imm (rt_SMSP=1), no weight regs/loads.
__device__ constexpr float WT[KS] = {
    0.00016011f, 0.00051415f, 0.00147746f, 0.00379911f, 0.00874165f,
    0.01799911f, 0.03316293f, 0.05467645f, 0.08066640f, 0.10649510f,
    0.12580922f, 0.13299641f, 0.12580922f, 0.10649510f, 0.08066640f,
    0.05467645f, 0.03316293f, 0.01799911f, 0.00874165f, 0.00379911f,
    0.00147746f, 0.00051415f, 0.00016011f
};

__global__ void __launch_bounds__(NTHR, 4)
saliency_kernel(const float* __restrict__ points, float* __restrict__ out) {
    __shared__ __align__(16) float s_hist[HIST_F];  // [STRIP][W_] point counts
    __shared__ __align__(16) float s_B[B_F];        // [RPB][BW]; stored idx = col+HALF

    const int tidx = threadIdx.x;
    const int b    = blockIdx.x / TILES_Y;
    const int tile = blockIdx.x % TILES_Y;
    const int r0   = tile * RPB;
    const int ylo  = r0 - HALF;                     // hist row 0 == global row ylo

    // ---- Prefetch this thread's 4 points (2 float4 = 4 (x,y) pairs) ----
    const float4* p4 = reinterpret_cast<const float4*>(points + b * N_ * 2);
    float4 pa = p4[tidx];
    float4 pb = p4[tidx + NTHR];

    // ---- Phase 0: zero hist + B halo ----
    {
        float4 z4 = make_float4(0.f, 0.f, 0.f, 0.f);
        float4* h4 = reinterpret_cast<float4*>(s_hist);
        #pragma unroll
        for (int k = tidx; k < HIST_F / 4; k += NTHR) h4[k] = z4;
        // B halo: stored idx [0..10] (cols -11..-1) and [235..246] (cols 224..235)
        if (tidx < RPB * KS) {                      // 322 halo cells
            int r = tidx / KS, ci = tidx % KS;
            int idx = (ci < HALF) ? ci : (W_ + ci); // 0..10 or 235..246
            s_B[r * BW + idx] = 0.f;
        }
    }
    __syncthreads();

    // ---- Phase 1: histogram scatter — one smem atomic per matching point ----
    {
        #pragma unroll
        for (int q = 0; q < 4; q++) {
            float px = (q == 0) ? pa.x : (q == 1) ? pa.z : (q == 2) ? pb.x : pb.z;
            float py = (q == 0) ? pa.y : (q == 1) ? pa.w : (q == 2) ? pb.y : pb.w;
            int x = (int)(px * (float)W_);  // truncation == astype(int32), nonneg
            int y = (int)(py * (float)H_);
            int u = y - ylo;
            if ((unsigned)u < (unsigned)STRIP &&
                (unsigned)x < (unsigned)W_ && (unsigned)y < (unsigned)H_)
                atomicAdd(&s_hist[u * W_ + x], 1.0f);
        }
    }
    __syncthreads();

    // ---- Phase 2: y-conv, float2 cols x 7 rows, FFMA-imm ----
    // B[rl][col c..c+1] = sum_j WT[j] * hist[rl+j][c..c+1]
    if (tidx < 2 * W2) {                            // 224 units
        int c2  = tidx % W2;
        int rl0 = (tidx / W2) * YRT;

        const float2* h2 = reinterpret_cast<const float2*>(s_hist) + c2;
        float2 acc[YRT];
        #pragma unroll
        for (int k = 0; k < YRT; k++) acc[k] = make_float2(0.f, 0.f);

        #pragma unroll
        for (int u = 0; u < YRT + KS - 1; u++) {    // 29 strip rows
            float2 v = h2[(rl0 + u) * W2];
            #pragma unroll
            for (int k = 0; k < YRT; k++) {
                int j = u - k;                      // compile-time per (u,k)
                if (j >= 0 && j < KS) {
                    acc[k].x = fmaf(WT[j], v.x, acc[k].x);  // FFMA-imm
                    acc[k].y = fmaf(WT[j], v.y, acc[k].y);
                }
            }
        }
        #pragma unroll
        for (int k = 0; k < YRT; k++) {
            float* dst = s_B + (rl0 + k) * BW + HALF + c2 * 2;
            dst[0] = acc[k].x;
            dst[1] = acc[k].y;
        }
    }
    __syncthreads();

    // ---- Phase 3: x-conv, 14 cols per unit, single pass, FFMA-imm ----
    // out[r][c0+k] = sum_j WT[j] * B[r][c0+k-11+j]  -> brow[k+j], stored-idx space
    if (tidx < RPB * XTILES) {                      // 224 units
        int r  = tidx % RPB;                        // lane stride BW=247 -> coprime banks
        int ct = tidx / RPB;
        int c0 = ct * XT;

        const float* brow = s_B + r * BW + c0;      // brow[u], u in [0, 35]
        float acc[XT];
        #pragma unroll
        for (int k = 0; k < XT; k++) acc[k] = 0.f;

        #pragma unroll
        for (int u = 0; u < XT + KS - 1; u++) {     // 36 loads
            float v = brow[u];
            #pragma unroll
            for (int k = 0; k < XT; k++) {
                int j = u - k;
                if (j >= 0 && j < KS)
                    acc[k] = fmaf(WT[j], v, acc[k]);  // FFMA-imm
            }
        }

        float* orow = out + (b * H_ + r0 + r) * W_ + c0;  // 56B-aligned
        #pragma unroll
        for (int k = 0; k < XT / 2; k++)
            reinterpret_cast<float2*>(orow)[k] = make_float2(acc[2*k], acc[2*k+1]);
    }
}

extern "C" void kernel_launch(void* const* d_in, const int* in_sizes, int n_in,
                              void* d_out, int out_size) {
    const float* points = (const float*)d_in[1];  // d_in[0] = feature_map (unused)
    float* out = (float*)d_out;
    saliency_kernel<<<NBLK, NTHR>>>(points, out);
}